// round 9
// baseline (speedup 1.0000x reference)
#include <cuda_runtime.h>
#include <cuda_bf16.h>

#define NNODES 50000
#define NEDGES 600000
#define CHUNK  1024
#define NCHUNK 49   // ceil(50000/1024)
#define NSPLIT 25024         // 64-aligned node split for tail pipeline
#define NREST  (NNODES - NSPLIT)

// ---------------- scratch (device globals) -----------------------------------
__device__ int g_is64;
__device__ int g_cnt [NNODES];
__device__ int g_off [NNODES];
__device__ int g_cur [NNODES];
__device__ __align__(8) int g_src32[NEDGES];
__device__ __align__(8) int g_dst32[NEDGES];
__device__ int g_eidx [NEDGES];
__device__ int g_chunksum[64];
__device__ __align__(16) float g_u[NNODES * 128];   // x @ Wl1
__device__ __align__(16) float g_v[NNODES * 128];   // x @ Wr1
__device__ __align__(16) float g_h[NNODES * 128];   // layer1 output (post relu)
__device__ __align__(16) float g_p[NNODES * 64];    // h @ Wl2
__device__ __align__(16) float g_q[NNODES * 64];    // h @ Wr2 + bl2

// ---------------- f32x2 helpers -----------------------------------------------
typedef unsigned long long ull;
__device__ __forceinline__ ull pk2(float x, float y) {
    ull r; asm("mov.b64 %0, {%1, %2};" : "=l"(r) : "f"(x), "f"(y)); return r;
}
__device__ __forceinline__ ull pkdup(float x) {
    ull r; asm("mov.b64 %0, {%1, %1};" : "=l"(r) : "f"(x)); return r;
}
__device__ __forceinline__ void ffma2(ull& d, ull a, ull b) {
    asm("fma.rn.f32x2 %0, %1, %2, %0;" : "+l"(d) : "l"(a), "l"(b));
}
__device__ __forceinline__ float2 unpk(ull v) {
    float2 r; asm("mov.b64 {%0, %1}, %2;" : "=f"(r.x), "=f"(r.y) : "l"(v)); return r;
}

// ---------------- init: zero counts + dtype detect ---------------------------
__global__ void init_kernel(const int* __restrict__ ei32) {
    int i = blockIdx.x * blockDim.x + threadIdx.x;
    if (i < NNODES) g_cnt[i] = 0;
    if (i == 0) {
        int allzero = 1;
        #pragma unroll
        for (int j = 0; j < 64; j++)
            if (ei32[2 * j + 1] != 0) allzero = 0;
        g_is64 = allzero;
    }
}

// ---------------- hist: 2 edges per thread -----------------------------------
__global__ void hist_kernel(const void* __restrict__ ei) {
    int t = blockIdx.x * blockDim.x + threadIdx.x;
    int e = t * 2;
    if (e >= NEDGES) return;
    int s0, s1, d0, d1;
    if (g_is64) {
        const long long* e64 = (const long long*)ei;
        longlong2 ss = *(const longlong2*)(e64 + e);
        longlong2 dd = *(const longlong2*)(e64 + NEDGES + e);
        s0 = (int)ss.x; s1 = (int)ss.y; d0 = (int)dd.x; d1 = (int)dd.y;
    } else {
        const int* e32 = (const int*)ei;
        int2 ss = *(const int2*)(e32 + e);
        int2 dd = *(const int2*)(e32 + NEDGES + e);
        s0 = ss.x; s1 = ss.y; d0 = dd.x; d1 = dd.y;
    }
    s0 = min(max(s0, 0), NNODES - 1); s1 = min(max(s1, 0), NNODES - 1);
    d0 = min(max(d0, 0), NNODES - 1); d1 = min(max(d1, 0), NNODES - 1);
    *(int2*)(g_src32 + e) = make_int2(s0, s1);
    *(int2*)(g_dst32 + e) = make_int2(d0, d1);
    atomicAdd(&g_cnt[d0], 1);
    atomicAdd(&g_cnt[d1], 1);
}

// ---------------- scan phase 1: per-chunk sums --------------------------------
__global__ void scan_p1_kernel() {
    __shared__ int sm[CHUNK];
    int tid = threadIdx.x;
    int idx = blockIdx.x * CHUNK + tid;
    sm[tid] = (idx < NNODES) ? g_cnt[idx] : 0;
    __syncthreads();
    #pragma unroll
    for (int s = CHUNK / 2; s > 0; s >>= 1) {
        if (tid < s) sm[tid] += sm[tid + s];
        __syncthreads();
    }
    if (tid == 0) g_chunksum[blockIdx.x] = sm[0];
}

// ---------------- scan phase 2+3 merged: chunk offsets + local scan ----------
__global__ void scan_p23_kernel() {
    __shared__ int sums[64];
    __shared__ int sm[CHUNK];
    int tid = threadIdx.x;
    if (tid < 64) sums[tid] = (tid < NCHUNK) ? g_chunksum[tid] : 0;
    __syncthreads();
    if (tid == 0) {
        int run = 0;
        for (int i = 0; i < NCHUNK; i++) { int v = sums[i]; sums[i] = run; run += v; }
    }
    __syncthreads();
    int chunkoff = sums[blockIdx.x];

    int idx = blockIdx.x * CHUNK + tid;
    int v = (idx < NNODES) ? g_cnt[idx] : 0;
    sm[tid] = v;
    __syncthreads();
    #pragma unroll
    for (int d = 1; d < CHUNK; d <<= 1) {
        int t = (tid >= d) ? sm[tid - d] : 0;
        __syncthreads();
        sm[tid] += t;
        __syncthreads();
    }
    if (idx < NNODES) {
        int off = chunkoff + sm[tid] - v;   // exclusive
        g_off[idx] = off;
        g_cur[idx] = off;
    }
}

// ---------------- bucket fill: 2 edges per thread -----------------------------
__global__ void fill_kernel() {
    int t = blockIdx.x * blockDim.x + threadIdx.x;
    int e = t * 2;
    if (e >= NEDGES) return;
    int2 dd = *(const int2*)(g_dst32 + e);
    int2 ss = *(const int2*)(g_src32 + e);
    int pos0 = atomicAdd(&g_cur[dd.x], 1);
    if (pos0 >= 0 && pos0 < NEDGES) g_eidx[pos0] = ss.x;
    int pos1 = atomicAdd(&g_cur[dd.y], 1);
    if (pos1 >= 0 && pos1 < NEDGES) g_eidx[pos1] = ss.y;
}

// ---------------- GEMM X: u = x@Wl1 ; v = x@Wr1 (edge-independent) -----------
// BM=64, BN=256 (u cols 0..127, v cols 128..255), K=128.
// SMEM: Ws[128][256] 128KB + As[128][64] k-major 32KB = 160KB.
__global__ void __launch_bounds__(256, 1)
gemmX_kernel(const float4* __restrict__ x4,
             const float4* __restrict__ Wl1,   // [128][32] f4
             const float4* __restrict__ Wr1) { // [128][32] f4
    extern __shared__ float sm[];
    float* Ws = sm;                 // [128][256]
    float* As = sm + 128 * 256;     // [128][64]  k-major
    int tid = threadIdx.x;
    int tx = tid & 31, ty = tid >> 5;
    int m0 = blockIdx.x * 64;

    float4* Ws4 = (float4*)Ws;
    #pragma unroll
    for (int i = tid; i < 8192; i += 256) {
        int k = i >> 6, c = i & 63;
        Ws4[i] = (c < 32) ? Wl1[k * 32 + c] : Wr1[k * 32 + (c - 32)];
    }
    #pragma unroll
    for (int i = tid; i < 2048; i += 256) {
        int r = i & 63, c = i >> 6;   // c 0..31
        int m = m0 + r;
        float4 v = (m < NNODES) ? x4[m * 32 + c] : make_float4(0.f, 0.f, 0.f, 0.f);
        As[(4 * c + 0) * 64 + r] = v.x;
        As[(4 * c + 1) * 64 + r] = v.y;
        As[(4 * c + 2) * 64 + r] = v.z;
        As[(4 * c + 3) * 64 + r] = v.w;
    }
    __syncthreads();

    ull acc[4][8] = {};   // [m-pair][n: 0..3 u, 4..7 v]
    #pragma unroll 4
    for (int k = 0; k < 128; k++) {
        const float* arow = As + k * 64 + ty * 8;
        float4 a0 = *(const float4*)arow;
        float4 a1 = *(const float4*)(arow + 4);
        ull ap[4];
        ap[0] = pk2(a0.x, a0.y); ap[1] = pk2(a0.z, a0.w);
        ap[2] = pk2(a1.x, a1.y); ap[3] = pk2(a1.z, a1.w);
        float4 bu = Ws4[k * 64 + tx];
        float4 bv = Ws4[k * 64 + 32 + tx];
        ull bd[8];
        bd[0] = pkdup(bu.x); bd[1] = pkdup(bu.y); bd[2] = pkdup(bu.z); bd[3] = pkdup(bu.w);
        bd[4] = pkdup(bv.x); bd[5] = pkdup(bv.y); bd[6] = pkdup(bv.z); bd[7] = pkdup(bv.w);
        #pragma unroll
        for (int ip = 0; ip < 4; ip++) {
            #pragma unroll
            for (int j = 0; j < 8; j++) ffma2(acc[ip][j], ap[ip], bd[j]);
        }
    }

    float4* u4 = (float4*)g_u;
    float4* v4 = (float4*)g_v;
    #pragma unroll
    for (int ip = 0; ip < 4; ip++) {
        float2 c0 = unpk(acc[ip][0]), c1 = unpk(acc[ip][1]);
        float2 c2 = unpk(acc[ip][2]), c3 = unpk(acc[ip][3]);
        float2 c4 = unpk(acc[ip][4]), c5 = unpk(acc[ip][5]);
        float2 c6 = unpk(acc[ip][6]), c7 = unpk(acc[ip][7]);
        int m = m0 + ty * 8 + 2 * ip;
        if (m < NNODES) {
            u4[m * 32 + tx] = make_float4(c0.x, c1.x, c2.x, c3.x);
            v4[m * 32 + tx] = make_float4(c4.x, c5.x, c6.x, c7.x);
        }
        if (m + 1 < NNODES) {
            u4[(m + 1) * 32 + tx] = make_float4(c0.y, c1.y, c2.y, c3.y);
            v4[(m + 1) * 32 + tx] = make_float4(c4.y, c5.y, c6.y, c7.y);
        }
    }
}

// ---------------- gatherH: h = relu(mean_agg(u) + bl1 + v), node range -------
__global__ void gatherH_kernel(const float4* __restrict__ bl1, int nbase, int ncount) {
    int w    = ((blockIdx.x * blockDim.x + threadIdx.x) >> 5);
    int lane = threadIdx.x & 31;
    if (w >= ncount) return;
    w += nbase;
    int beg = g_off[w];
    int c   = g_cnt[w];
    const float4* u4 = (const float4*)g_u;
    float4 acc = make_float4(0.f, 0.f, 0.f, 0.f);
    int i = 0;
    for (; i + 3 < c; i += 4) {
        int s0 = g_eidx[beg + i];
        int s1 = g_eidx[beg + i + 1];
        int s2 = g_eidx[beg + i + 2];
        int s3 = g_eidx[beg + i + 3];
        float4 v0 = u4[s0 * 32 + lane];
        float4 v1 = u4[s1 * 32 + lane];
        float4 v2 = u4[s2 * 32 + lane];
        float4 v3 = u4[s3 * 32 + lane];
        acc.x += (v0.x + v1.x) + (v2.x + v3.x);
        acc.y += (v0.y + v1.y) + (v2.y + v3.y);
        acc.z += (v0.z + v1.z) + (v2.z + v3.z);
        acc.w += (v0.w + v1.w) + (v2.w + v3.w);
    }
    for (; i < c; i++) {
        int s0 = g_eidx[beg + i];
        float4 v0 = u4[s0 * 32 + lane];
        acc.x += v0.x; acc.y += v0.y; acc.z += v0.z; acc.w += v0.w;
    }
    float rd = 1.0f / (float)max(c, 1);
    float4 b  = bl1[lane];
    float4 vv = ((const float4*)g_v)[w * 32 + lane];
    float4 o;
    o.x = fmaxf(acc.x * rd + b.x + vv.x, 0.f);
    o.y = fmaxf(acc.y * rd + b.y + vv.y, 0.f);
    o.z = fmaxf(acc.z * rd + b.z + vv.z, 0.f);
    o.w = fmaxf(acc.w * rd + b.w + vv.w, 0.f);
    ((float4*)g_h)[w * 32 + lane] = o;
}

// ---------------- GEMM2: p = h@Wl2 ; q = h@Wr2 + bl2 (node range) ------------
// BM=64, BN=128 (cols 0..63 -> p, 64..127 -> q), K=128.
// SMEM: Ws 64KB + As 32KB = 96KB -> 2 blocks/SM.
__global__ void __launch_bounds__(256, 2)
gemm2_kernel(const float4* __restrict__ Wl2,   // [128][16] f4
             const float4* __restrict__ Wr2,   // [128][16] f4
             const float4* __restrict__ bl2,   // [16] f4
             int mbase) {
    extern __shared__ float sm[];
    float* Ws = sm;                 // [128][128]
    float* As = sm + 128 * 128;     // [128][64]  k-major
    int tid = threadIdx.x;
    int tx = tid & 31, ty = tid >> 5;
    int m0 = mbase + blockIdx.x * 64;

    float4* Ws4 = (float4*)Ws;
    #pragma unroll
    for (int i = tid; i < 4096; i += 256) {
        int k = i >> 5, c = i & 31;
        Ws4[i] = (c < 16) ? Wl2[k * 16 + c] : Wr2[k * 16 + (c - 16)];
    }
    const float4* h4 = (const float4*)g_h;
    #pragma unroll
    for (int i = tid; i < 2048; i += 256) {
        int r = i & 63, c = i >> 6;   // c 0..31
        int m = m0 + r;
        float4 v = (m < NNODES) ? h4[m * 32 + c] : make_float4(0.f, 0.f, 0.f, 0.f);
        As[(4 * c + 0) * 64 + r] = v.x;
        As[(4 * c + 1) * 64 + r] = v.y;
        As[(4 * c + 2) * 64 + r] = v.z;
        As[(4 * c + 3) * 64 + r] = v.w;
    }
    __syncthreads();

    ull acc[4][4] = {};
    #pragma unroll 4
    for (int k = 0; k < 128; k++) {
        const float* arow = As + k * 64 + ty * 8;
        float4 a0 = *(const float4*)arow;
        float4 a1 = *(const float4*)(arow + 4);
        ull ap[4];
        ap[0] = pk2(a0.x, a0.y); ap[1] = pk2(a0.z, a0.w);
        ap[2] = pk2(a1.x, a1.y); ap[3] = pk2(a1.z, a1.w);
        float4 b = Ws4[k * 32 + tx];
        ull bd0 = pkdup(b.x), bd1 = pkdup(b.y), bd2 = pkdup(b.z), bd3 = pkdup(b.w);
        #pragma unroll
        for (int ip = 0; ip < 4; ip++) {
            ffma2(acc[ip][0], ap[ip], bd0);
            ffma2(acc[ip][1], ap[ip], bd1);
            ffma2(acc[ip][2], ap[ip], bd2);
            ffma2(acc[ip][3], ap[ip], bd3);
        }
    }

    float4* p4 = (float4*)g_p;
    float4* q4 = (float4*)g_q;
    if (tx < 16) {
        #pragma unroll
        for (int ip = 0; ip < 4; ip++) {
            float2 c0 = unpk(acc[ip][0]), c1 = unpk(acc[ip][1]);
            float2 c2 = unpk(acc[ip][2]), c3 = unpk(acc[ip][3]);
            int m = m0 + ty * 8 + 2 * ip;
            if (m < NNODES)
                p4[m * 16 + tx] = make_float4(c0.x, c1.x, c2.x, c3.x);
            if (m + 1 < NNODES)
                p4[(m + 1) * 16 + tx] = make_float4(c0.y, c1.y, c2.y, c3.y);
        }
    } else {
        float4 bias = bl2[tx - 16];
        #pragma unroll
        for (int ip = 0; ip < 4; ip++) {
            float2 c0 = unpk(acc[ip][0]), c1 = unpk(acc[ip][1]);
            float2 c2 = unpk(acc[ip][2]), c3 = unpk(acc[ip][3]);
            int m = m0 + ty * 8 + 2 * ip;
            if (m < NNODES)
                q4[m * 16 + (tx - 16)] = make_float4(c0.x + bias.x, c1.x + bias.y,
                                                     c2.x + bias.z, c3.x + bias.w);
            if (m + 1 < NNODES)
                q4[(m + 1) * 16 + (tx - 16)] = make_float4(c0.y + bias.x, c1.y + bias.y,
                                                           c2.y + bias.z, c3.y + bias.w);
        }
    }
}

// ---------------- gather layer 2 + log_softmax (fused) -----------------------
__global__ void gather2_final_kernel(float* __restrict__ out) {
    int w    = (blockIdx.x * blockDim.x + threadIdx.x) >> 5;
    int lane = threadIdx.x & 31;
    if (w >= NNODES) return;
    int beg = g_off[w];
    int c   = g_cnt[w];
    const float2* p2 = (const float2*)g_p;
    float2 acc = make_float2(0.f, 0.f);
    int i = 0;
    for (; i + 3 < c; i += 4) {
        int s0 = g_eidx[beg + i];
        int s1 = g_eidx[beg + i + 1];
        int s2 = g_eidx[beg + i + 2];
        int s3 = g_eidx[beg + i + 3];
        float2 v0 = p2[s0 * 32 + lane];
        float2 v1 = p2[s1 * 32 + lane];
        float2 v2 = p2[s2 * 32 + lane];
        float2 v3 = p2[s3 * 32 + lane];
        acc.x += (v0.x + v1.x) + (v2.x + v3.x);
        acc.y += (v0.y + v1.y) + (v2.y + v3.y);
    }
    for (; i < c; i++) {
        int s0 = g_eidx[beg + i];
        float2 v0 = p2[s0 * 32 + lane];
        acc.x += v0.x; acc.y += v0.y;
    }
    float rd = 1.0f / (float)max(c, 1);
    float2 q = ((const float2*)g_q)[w * 32 + lane];
    float v0 = acc.x * rd + q.x;
    float v1 = acc.y * rd + q.y;

    float mx = fmaxf(v0, v1);
    #pragma unroll
    for (int o = 16; o; o >>= 1) mx = fmaxf(mx, __shfl_xor_sync(0xffffffffu, mx, o));
    float s = expf(v0 - mx) + expf(v1 - mx);
    #pragma unroll
    for (int o = 16; o; o >>= 1) s += __shfl_xor_sync(0xffffffffu, s, o);
    float ls = logf(s) + mx;

    ((float2*)out)[w * 32 + lane] = make_float2(v0 - ls, v1 - ls);
}

// ---------------- stream/event resources (created once, pre-checkpoint) ------
static cudaStream_t g_s2   = nullptr;
static cudaEvent_t  g_fork = nullptr;
static cudaEvent_t  g_join = nullptr;   // CSR done
static cudaEvent_t  g_ex   = nullptr;   // gemmX done
static cudaEvent_t  g_ehB  = nullptr;   // gatherH_B done

static void ensure_resources() {
    if (!g_s2) {
        cudaStreamCreateWithFlags(&g_s2, cudaStreamNonBlocking);
        cudaEventCreateWithFlags(&g_fork, cudaEventDisableTiming);
        cudaEventCreateWithFlags(&g_join, cudaEventDisableTiming);
        cudaEventCreateWithFlags(&g_ex,   cudaEventDisableTiming);
        cudaEventCreateWithFlags(&g_ehB,  cudaEventDisableTiming);
    }
}
namespace { struct ResInit { ResInit() { ensure_resources(); } } g_resinit; }

// ---------------- launch ------------------------------------------------------
extern "C" void kernel_launch(void* const* d_in, const int* in_sizes, int n_in,
                              void* d_out, int out_size) {
    const float4* x4   = (const float4*)d_in[0];
    const void*   ei   = d_in[1];
    const float4* Wl1  = (const float4*)d_in[2];
    const float4* bl1  = (const float4*)d_in[3];
    const float4* Wr1  = (const float4*)d_in[4];
    const float4* Wl2  = (const float4*)d_in[5];
    const float4* bl2  = (const float4*)d_in[6];
    const float4* Wr2  = (const float4*)d_in[7];
    float*        out  = (float*)d_out;

    ensure_resources();
    cudaFuncSetAttribute(gemmX_kernel, cudaFuncAttributeMaxDynamicSharedMemorySize, 163840);
    cudaFuncSetAttribute(gemm2_kernel, cudaFuncAttributeMaxDynamicSharedMemorySize, 98304);

    // ---- fork: CSR build on g_s2, concurrent with gemmX on the main stream ----
    cudaEventRecord(g_fork, 0);
    cudaStreamWaitEvent(g_s2, g_fork, 0);

    init_kernel<<<(NNODES + 255) / 256, 256, 0, g_s2>>>((const int*)ei);
    hist_kernel<<<(NEDGES / 2 + 255) / 256, 256, 0, g_s2>>>(ei);
    scan_p1_kernel<<<NCHUNK, CHUNK, 0, g_s2>>>();
    scan_p23_kernel<<<NCHUNK, CHUNK, 0, g_s2>>>();
    fill_kernel<<<(NEDGES / 2 + 255) / 256, 256, 0, g_s2>>>();
    cudaEventRecord(g_join, g_s2);

    gemmX_kernel<<<(NNODES + 63) / 64, 256, 163840>>>(x4, Wl1, Wr1);
    cudaEventRecord(g_ex, 0);

    // ---- s0 joins CSR; gatherH_A on s0 -----------------------------------------
    cudaStreamWaitEvent(0, g_join, 0);
    gatherH_kernel<<<(NSPLIT * 32 + 255) / 256, 256>>>(bl1, 0, NSPLIT);

    // ---- gatherH_B on s2 (needs gemmX + CSR(already on s2)) --------------------
    cudaStreamWaitEvent(g_s2, g_ex, 0);
    gatherH_kernel<<<(NREST * 32 + 255) / 256, 256, 0, g_s2>>>(bl1, NSPLIT, NREST);
    cudaEventRecord(g_ehB, g_s2);

    // ---- gemm2_A on s0, concurrent with gatherH_B on s2 ------------------------
    gemm2_kernel<<<NSPLIT / 64, 256, 98304>>>(Wl2, Wr2, bl2, 0);

    // ---- gemm2_B after gatherH_B -----------------------------------------------
    cudaStreamWaitEvent(0, g_ehB, 0);
    gemm2_kernel<<<(NREST + 63) / 64, 256, 98304>>>(Wl2, Wr2, bl2, NSPLIT);

    // ---- final ------------------------------------------------------------------
    gather2_final_kernel<<<(NNODES * 32 + 255) / 256, 256>>>(out);
}

// round 10
// speedup vs baseline: 1.0596x; 1.0596x over previous
#include <cuda_runtime.h>
#include <cuda_bf16.h>
#include <cuda_fp16.h>

#define NNODES 50000
#define NEDGES 600000
#define CHUNK  1024
#define NCHUNK 49   // ceil(50000/1024)

// ---------------- scratch (device globals) -----------------------------------
__device__ int g_is64;
__device__ int g_cnt [NNODES];
__device__ int g_off [NNODES];
__device__ int g_cur [NNODES];
__device__ __align__(8) int g_src32[NEDGES];
__device__ __align__(8) int g_dst32[NEDGES];
__device__ int g_eidx [NEDGES];
__device__ int g_chunksum[64];
__device__ __align__(16) __half g_uh[NNODES * 128];  // x @ Wl1   (fp16)
__device__ __align__(16) float  g_v [NNODES * 128];  // x @ Wr1   (fp32)
__device__ __align__(16) float  g_h [NNODES * 128];  // layer1 out (post relu)
__device__ __align__(16) __half g_ph[NNODES * 64];   // h @ Wl2   (fp16)
__device__ __align__(16) float  g_q [NNODES * 64];   // h @ Wr2 + bl2

// ---------------- f32x2 helpers -----------------------------------------------
typedef unsigned long long ull;
__device__ __forceinline__ ull pk2(float x, float y) {
    ull r; asm("mov.b64 %0, {%1, %2};" : "=l"(r) : "f"(x), "f"(y)); return r;
}
__device__ __forceinline__ ull pkdup(float x) {
    ull r; asm("mov.b64 %0, {%1, %1};" : "=l"(r) : "f"(x)); return r;
}
__device__ __forceinline__ void ffma2(ull& d, ull a, ull b) {
    asm("fma.rn.f32x2 %0, %1, %2, %0;" : "+l"(d) : "l"(a), "l"(b));
}
__device__ __forceinline__ float2 unpk(ull v) {
    float2 r; asm("mov.b64 {%0, %1}, %2;" : "=f"(r.x), "=f"(r.y) : "l"(v)); return r;
}
__device__ __forceinline__ unsigned h2u(__half2 h) {
    unsigned u; asm("mov.b32 %0, %1;" : "=r"(u) : "r"(*(unsigned*)&h)); return u;
}

// ---------------- init: zero counts + dtype detect ---------------------------
__global__ void init_kernel(const int* __restrict__ ei32) {
    int i = blockIdx.x * blockDim.x + threadIdx.x;
    if (i < NNODES) g_cnt[i] = 0;
    if (i == 0) {
        int allzero = 1;
        #pragma unroll
        for (int j = 0; j < 64; j++)
            if (ei32[2 * j + 1] != 0) allzero = 0;
        g_is64 = allzero;
    }
}

// ---------------- hist: 2 edges per thread -----------------------------------
__global__ void hist_kernel(const void* __restrict__ ei) {
    int t = blockIdx.x * blockDim.x + threadIdx.x;
    int e = t * 2;
    if (e >= NEDGES) return;
    int s0, s1, d0, d1;
    if (g_is64) {
        const long long* e64 = (const long long*)ei;
        longlong2 ss = *(const longlong2*)(e64 + e);
        longlong2 dd = *(const longlong2*)(e64 + NEDGES + e);
        s0 = (int)ss.x; s1 = (int)ss.y; d0 = (int)dd.x; d1 = (int)dd.y;
    } else {
        const int* e32 = (const int*)ei;
        int2 ss = *(const int2*)(e32 + e);
        int2 dd = *(const int2*)(e32 + NEDGES + e);
        s0 = ss.x; s1 = ss.y; d0 = dd.x; d1 = dd.y;
    }
    s0 = min(max(s0, 0), NNODES - 1); s1 = min(max(s1, 0), NNODES - 1);
    d0 = min(max(d0, 0), NNODES - 1); d1 = min(max(d1, 0), NNODES - 1);
    *(int2*)(g_src32 + e) = make_int2(s0, s1);
    *(int2*)(g_dst32 + e) = make_int2(d0, d1);
    atomicAdd(&g_cnt[d0], 1);
    atomicAdd(&g_cnt[d1], 1);
}

// ---------------- scan phase 1: per-chunk sums --------------------------------
__global__ void scan_p1_kernel() {
    __shared__ int sm[CHUNK];
    int tid = threadIdx.x;
    int idx = blockIdx.x * CHUNK + tid;
    sm[tid] = (idx < NNODES) ? g_cnt[idx] : 0;
    __syncthreads();
    #pragma unroll
    for (int s = CHUNK / 2; s > 0; s >>= 1) {
        if (tid < s) sm[tid] += sm[tid + s];
        __syncthreads();
    }
    if (tid == 0) g_chunksum[blockIdx.x] = sm[0];
}

// ---------------- scan phase 2+3 merged ---------------------------------------
__global__ void scan_p23_kernel() {
    __shared__ int sums[64];
    __shared__ int sm[CHUNK];
    int tid = threadIdx.x;
    if (tid < 64) sums[tid] = (tid < NCHUNK) ? g_chunksum[tid] : 0;
    __syncthreads();
    if (tid == 0) {
        int run = 0;
        for (int i = 0; i < NCHUNK; i++) { int v = sums[i]; sums[i] = run; run += v; }
    }
    __syncthreads();
    int chunkoff = sums[blockIdx.x];

    int idx = blockIdx.x * CHUNK + tid;
    int v = (idx < NNODES) ? g_cnt[idx] : 0;
    sm[tid] = v;
    __syncthreads();
    #pragma unroll
    for (int d = 1; d < CHUNK; d <<= 1) {
        int t = (tid >= d) ? sm[tid - d] : 0;
        __syncthreads();
        sm[tid] += t;
        __syncthreads();
    }
    if (idx < NNODES) {
        int off = chunkoff + sm[tid] - v;   // exclusive
        g_off[idx] = off;
        g_cur[idx] = off;
    }
}

// ---------------- bucket fill: 2 edges per thread -----------------------------
__global__ void fill_kernel() {
    int t = blockIdx.x * blockDim.x + threadIdx.x;
    int e = t * 2;
    if (e >= NEDGES) return;
    int2 dd = *(const int2*)(g_dst32 + e);
    int2 ss = *(const int2*)(g_src32 + e);
    int pos0 = atomicAdd(&g_cur[dd.x], 1);
    if (pos0 >= 0 && pos0 < NEDGES) g_eidx[pos0] = ss.x;
    int pos1 = atomicAdd(&g_cur[dd.y], 1);
    if (pos1 >= 0 && pos1 < NEDGES) g_eidx[pos1] = ss.y;
}

// ---------------- GEMM X: u = x@Wl1 (fp16 out) ; v = x@Wr1 (fp32 out) --------
// BM=64, BN=256, K=128. SMEM: Ws 128KB + As 32KB = 160KB.
__global__ void __launch_bounds__(256, 1)
gemmX_kernel(const float4* __restrict__ x4,
             const float4* __restrict__ Wl1,   // [128][32] f4
             const float4* __restrict__ Wr1) { // [128][32] f4
    extern __shared__ float sm[];
    float* Ws = sm;                 // [128][256]
    float* As = sm + 128 * 256;     // [128][64]  k-major
    int tid = threadIdx.x;
    int tx = tid & 31, ty = tid >> 5;
    int m0 = blockIdx.x * 64;

    float4* Ws4 = (float4*)Ws;
    #pragma unroll
    for (int i = tid; i < 8192; i += 256) {
        int k = i >> 6, c = i & 63;
        Ws4[i] = (c < 32) ? Wl1[k * 32 + c] : Wr1[k * 32 + (c - 32)];
    }
    #pragma unroll
    for (int i = tid; i < 2048; i += 256) {
        int r = i & 63, c = i >> 6;   // c 0..31
        int m = m0 + r;
        float4 v = (m < NNODES) ? x4[m * 32 + c] : make_float4(0.f, 0.f, 0.f, 0.f);
        As[(4 * c + 0) * 64 + r] = v.x;
        As[(4 * c + 1) * 64 + r] = v.y;
        As[(4 * c + 2) * 64 + r] = v.z;
        As[(4 * c + 3) * 64 + r] = v.w;
    }
    __syncthreads();

    ull acc[4][8] = {};   // [m-pair][n: 0..3 u, 4..7 v]
    #pragma unroll 4
    for (int k = 0; k < 128; k++) {
        const float* arow = As + k * 64 + ty * 8;
        float4 a0 = *(const float4*)arow;
        float4 a1 = *(const float4*)(arow + 4);
        ull ap[4];
        ap[0] = pk2(a0.x, a0.y); ap[1] = pk2(a0.z, a0.w);
        ap[2] = pk2(a1.x, a1.y); ap[3] = pk2(a1.z, a1.w);
        float4 bu = Ws4[k * 64 + tx];
        float4 bv = Ws4[k * 64 + 32 + tx];
        ull bd[8];
        bd[0] = pkdup(bu.x); bd[1] = pkdup(bu.y); bd[2] = pkdup(bu.z); bd[3] = pkdup(bu.w);
        bd[4] = pkdup(bv.x); bd[5] = pkdup(bv.y); bd[6] = pkdup(bv.z); bd[7] = pkdup(bv.w);
        #pragma unroll
        for (int ip = 0; ip < 4; ip++) {
            #pragma unroll
            for (int j = 0; j < 8; j++) ffma2(acc[ip][j], ap[ip], bd[j]);
        }
    }

    uint2*  uh2 = (uint2*)g_uh;   // 4 halves per entry, 32 per row
    float4* v4  = (float4*)g_v;
    #pragma unroll
    for (int ip = 0; ip < 4; ip++) {
        float2 c0 = unpk(acc[ip][0]), c1 = unpk(acc[ip][1]);
        float2 c2 = unpk(acc[ip][2]), c3 = unpk(acc[ip][3]);
        float2 c4 = unpk(acc[ip][4]), c5 = unpk(acc[ip][5]);
        float2 c6 = unpk(acc[ip][6]), c7 = unpk(acc[ip][7]);
        int m = m0 + ty * 8 + 2 * ip;
        if (m < NNODES) {
            uint2 pu;
            pu.x = h2u(__floats2half2_rn(c0.x, c1.x));
            pu.y = h2u(__floats2half2_rn(c2.x, c3.x));
            uh2[m * 32 + tx] = pu;
            v4[m * 32 + tx] = make_float4(c4.x, c5.x, c6.x, c7.x);
        }
        if (m + 1 < NNODES) {
            uint2 pu;
            pu.x = h2u(__floats2half2_rn(c0.y, c1.y));
            pu.y = h2u(__floats2half2_rn(c2.y, c3.y));
            uh2[(m + 1) * 32 + tx] = pu;
            v4[(m + 1) * 32 + tx] = make_float4(c4.y, c5.y, c6.y, c7.y);
        }
    }
}

// ---------------- gatherH: h = relu(mean_agg(u_fp16) + bl1 + v) --------------
__global__ void gatherH_kernel(const float4* __restrict__ bl1) {
    int w    = (blockIdx.x * blockDim.x + threadIdx.x) >> 5;
    int lane = threadIdx.x & 31;
    if (w >= NNODES) return;
    int beg = g_off[w];
    int c   = g_cnt[w];
    const uint2* uh2 = (const uint2*)g_uh;
    float4 acc = make_float4(0.f, 0.f, 0.f, 0.f);
    int i = 0;
    for (; i + 3 < c; i += 4) {
        int s0 = g_eidx[beg + i];
        int s1 = g_eidx[beg + i + 1];
        int s2 = g_eidx[beg + i + 2];
        int s3 = g_eidx[beg + i + 3];
        uint2 r0 = uh2[s0 * 32 + lane];
        uint2 r1 = uh2[s1 * 32 + lane];
        uint2 r2 = uh2[s2 * 32 + lane];
        uint2 r3 = uh2[s3 * 32 + lane];
        float2 f;
        f = __half22float2(*(__half2*)&r0.x); acc.x += f.x; acc.y += f.y;
        f = __half22float2(*(__half2*)&r0.y); acc.z += f.x; acc.w += f.y;
        f = __half22float2(*(__half2*)&r1.x); acc.x += f.x; acc.y += f.y;
        f = __half22float2(*(__half2*)&r1.y); acc.z += f.x; acc.w += f.y;
        f = __half22float2(*(__half2*)&r2.x); acc.x += f.x; acc.y += f.y;
        f = __half22float2(*(__half2*)&r2.y); acc.z += f.x; acc.w += f.y;
        f = __half22float2(*(__half2*)&r3.x); acc.x += f.x; acc.y += f.y;
        f = __half22float2(*(__half2*)&r3.y); acc.z += f.x; acc.w += f.y;
    }
    for (; i < c; i++) {
        int s0 = g_eidx[beg + i];
        uint2 r0 = uh2[s0 * 32 + lane];
        float2 f;
        f = __half22float2(*(__half2*)&r0.x); acc.x += f.x; acc.y += f.y;
        f = __half22float2(*(__half2*)&r0.y); acc.z += f.x; acc.w += f.y;
    }
    float rd = 1.0f / (float)max(c, 1);
    float4 b  = bl1[lane];
    float4 vv = ((const float4*)g_v)[w * 32 + lane];
    float4 o;
    o.x = fmaxf(acc.x * rd + b.x + vv.x, 0.f);
    o.y = fmaxf(acc.y * rd + b.y + vv.y, 0.f);
    o.z = fmaxf(acc.z * rd + b.z + vv.z, 0.f);
    o.w = fmaxf(acc.w * rd + b.w + vv.w, 0.f);
    ((float4*)g_h)[w * 32 + lane] = o;
}

// ---------------- GEMM2: p = h@Wl2 (fp16 out) ; q = h@Wr2 + bl2 --------------
// BM=64, BN=128, K=128. SMEM: Ws 64KB + As 32KB = 96KB -> 2 blocks/SM.
__global__ void __launch_bounds__(256, 2)
gemm2_kernel(const float4* __restrict__ Wl2,   // [128][16] f4
             const float4* __restrict__ Wr2,   // [128][16] f4
             const float4* __restrict__ bl2) { // [16] f4
    extern __shared__ float sm[];
    float* Ws = sm;                 // [128][128]
    float* As = sm + 128 * 128;     // [128][64]  k-major
    int tid = threadIdx.x;
    int tx = tid & 31, ty = tid >> 5;
    int m0 = blockIdx.x * 64;

    float4* Ws4 = (float4*)Ws;
    #pragma unroll
    for (int i = tid; i < 4096; i += 256) {
        int k = i >> 5, c = i & 31;
        Ws4[i] = (c < 16) ? Wl2[k * 16 + c] : Wr2[k * 16 + (c - 16)];
    }
    const float4* h4 = (const float4*)g_h;
    #pragma unroll
    for (int i = tid; i < 2048; i += 256) {
        int r = i & 63, c = i >> 6;   // c 0..31
        int m = m0 + r;
        float4 v = (m < NNODES) ? h4[m * 32 + c] : make_float4(0.f, 0.f, 0.f, 0.f);
        As[(4 * c + 0) * 64 + r] = v.x;
        As[(4 * c + 1) * 64 + r] = v.y;
        As[(4 * c + 2) * 64 + r] = v.z;
        As[(4 * c + 3) * 64 + r] = v.w;
    }
    __syncthreads();

    ull acc[4][4] = {};
    #pragma unroll 4
    for (int k = 0; k < 128; k++) {
        const float* arow = As + k * 64 + ty * 8;
        float4 a0 = *(const float4*)arow;
        float4 a1 = *(const float4*)(arow + 4);
        ull ap[4];
        ap[0] = pk2(a0.x, a0.y); ap[1] = pk2(a0.z, a0.w);
        ap[2] = pk2(a1.x, a1.y); ap[3] = pk2(a1.z, a1.w);
        float4 b = Ws4[k * 32 + tx];
        ull bd0 = pkdup(b.x), bd1 = pkdup(b.y), bd2 = pkdup(b.z), bd3 = pkdup(b.w);
        #pragma unroll
        for (int ip = 0; ip < 4; ip++) {
            ffma2(acc[ip][0], ap[ip], bd0);
            ffma2(acc[ip][1], ap[ip], bd1);
            ffma2(acc[ip][2], ap[ip], bd2);
            ffma2(acc[ip][3], ap[ip], bd3);
        }
    }

    uint2*  ph2 = (uint2*)g_ph;   // 4 halves per entry, 16 per row
    float4* q4  = (float4*)g_q;
    if (tx < 16) {
        #pragma unroll
        for (int ip = 0; ip < 4; ip++) {
            float2 c0 = unpk(acc[ip][0]), c1 = unpk(acc[ip][1]);
            float2 c2 = unpk(acc[ip][2]), c3 = unpk(acc[ip][3]);
            int m = m0 + ty * 8 + 2 * ip;
            if (m < NNODES) {
                uint2 pu;
                pu.x = h2u(__floats2half2_rn(c0.x, c1.x));
                pu.y = h2u(__floats2half2_rn(c2.x, c3.x));
                ph2[m * 16 + tx] = pu;
            }
            if (m + 1 < NNODES) {
                uint2 pu;
                pu.x = h2u(__floats2half2_rn(c0.y, c1.y));
                pu.y = h2u(__floats2half2_rn(c2.y, c3.y));
                ph2[(m + 1) * 16 + tx] = pu;
            }
        }
    } else {
        float4 bias = bl2[tx - 16];
        #pragma unroll
        for (int ip = 0; ip < 4; ip++) {
            float2 c0 = unpk(acc[ip][0]), c1 = unpk(acc[ip][1]);
            float2 c2 = unpk(acc[ip][2]), c3 = unpk(acc[ip][3]);
            int m = m0 + ty * 8 + 2 * ip;
            if (m < NNODES)
                q4[m * 16 + (tx - 16)] = make_float4(c0.x + bias.x, c1.x + bias.y,
                                                     c2.x + bias.z, c3.x + bias.w);
            if (m + 1 < NNODES)
                q4[(m + 1) * 16 + (tx - 16)] = make_float4(c0.y + bias.x, c1.y + bias.y,
                                                           c2.y + bias.z, c3.y + bias.w);
        }
    }
}

// ---------------- gather layer 2 (fp16 p) + log_softmax (fused) ---------------
__global__ void gather2_final_kernel(float* __restrict__ out) {
    int w    = (blockIdx.x * blockDim.x + threadIdx.x) >> 5;
    int lane = threadIdx.x & 31;
    if (w >= NNODES) return;
    int beg = g_off[w];
    int c   = g_cnt[w];
    const unsigned* ph = (const unsigned*)g_ph;   // half2 per entry, 32 per row
    float2 acc = make_float2(0.f, 0.f);
    int i = 0;
    for (; i + 3 < c; i += 4) {
        int s0 = g_eidx[beg + i];
        int s1 = g_eidx[beg + i + 1];
        int s2 = g_eidx[beg + i + 2];
        int s3 = g_eidx[beg + i + 3];
        unsigned r0 = ph[s0 * 32 + lane];
        unsigned r1 = ph[s1 * 32 + lane];
        unsigned r2 = ph[s2 * 32 + lane];
        unsigned r3 = ph[s3 * 32 + lane];
        float2 f;
        f = __half22float2(*(__half2*)&r0); acc.x += f.x; acc.y += f.y;
        f = __half22float2(*(__half2*)&r1); acc.x += f.x; acc.y += f.y;
        f = __half22float2(*(__half2*)&r2); acc.x += f.x; acc.y += f.y;
        f = __half22float2(*(__half2*)&r3); acc.x += f.x; acc.y += f.y;
    }
    for (; i < c; i++) {
        int s0 = g_eidx[beg + i];
        unsigned r0 = ph[s0 * 32 + lane];
        float2 f = __half22float2(*(__half2*)&r0);
        acc.x += f.x; acc.y += f.y;
    }
    float rd = 1.0f / (float)max(c, 1);
    float2 q = ((const float2*)g_q)[w * 32 + lane];
    float v0 = acc.x * rd + q.x;
    float v1 = acc.y * rd + q.y;

    float mx = fmaxf(v0, v1);
    #pragma unroll
    for (int o = 16; o; o >>= 1) mx = fmaxf(mx, __shfl_xor_sync(0xffffffffu, mx, o));
    float s = expf(v0 - mx) + expf(v1 - mx);
    #pragma unroll
    for (int o = 16; o; o >>= 1) s += __shfl_xor_sync(0xffffffffu, s, o);
    float ls = logf(s) + mx;

    ((float2*)out)[w * 32 + lane] = make_float2(v0 - ls, v1 - ls);
}

// ---------------- stream/event resources (created once, pre-checkpoint) ------
static cudaStream_t g_s2   = nullptr;
static cudaEvent_t  g_fork = nullptr;
static cudaEvent_t  g_join = nullptr;

static void ensure_resources() {
    if (!g_s2) {
        cudaStreamCreateWithFlags(&g_s2, cudaStreamNonBlocking);
        cudaEventCreateWithFlags(&g_fork, cudaEventDisableTiming);
        cudaEventCreateWithFlags(&g_join, cudaEventDisableTiming);
    }
}
namespace { struct ResInit { ResInit() { ensure_resources(); } } g_resinit; }

// ---------------- launch ------------------------------------------------------
extern "C" void kernel_launch(void* const* d_in, const int* in_sizes, int n_in,
                              void* d_out, int out_size) {
    const float4* x4   = (const float4*)d_in[0];
    const void*   ei   = d_in[1];
    const float4* Wl1  = (const float4*)d_in[2];
    const float4* bl1  = (const float4*)d_in[3];
    const float4* Wr1  = (const float4*)d_in[4];
    const float4* Wl2  = (const float4*)d_in[5];
    const float4* bl2  = (const float4*)d_in[6];
    const float4* Wr2  = (const float4*)d_in[7];
    float*        out  = (float*)d_out;

    ensure_resources();
    cudaFuncSetAttribute(gemmX_kernel, cudaFuncAttributeMaxDynamicSharedMemorySize, 163840);
    cudaFuncSetAttribute(gemm2_kernel, cudaFuncAttributeMaxDynamicSharedMemorySize, 98304);

    // ---- fork: CSR build on g_s2, concurrent with gemmX on the main stream ----
    cudaEventRecord(g_fork, 0);
    cudaStreamWaitEvent(g_s2, g_fork, 0);

    init_kernel<<<(NNODES + 255) / 256, 256, 0, g_s2>>>((const int*)ei);
    hist_kernel<<<(NEDGES / 2 + 255) / 256, 256, 0, g_s2>>>(ei);
    scan_p1_kernel<<<NCHUNK, CHUNK, 0, g_s2>>>();
    scan_p23_kernel<<<NCHUNK, CHUNK, 0, g_s2>>>();
    fill_kernel<<<(NEDGES / 2 + 255) / 256, 256, 0, g_s2>>>();
    cudaEventRecord(g_join, g_s2);

    gemmX_kernel<<<(NNODES + 63) / 64, 256, 163840>>>(x4, Wl1, Wr1);

    // ---- join ----
    cudaStreamWaitEvent(0, g_join, 0);

    gatherH_kernel<<<(NNODES * 32 + 255) / 256, 256>>>(bl1);
    gemm2_kernel<<<(NNODES + 63) / 64, 256, 98304>>>(Wl2, Wr2, bl2);
    gather2_final_kernel<<<(NNODES * 32 + 255) / 256, 256>>>(out);
}

// round 11
// speedup vs baseline: 1.1359x; 1.0720x over previous
#include <cuda_runtime.h>
#include <cuda_bf16.h>
#include <cuda_fp16.h>

#define NNODES 50000
#define NEDGES 600000
#define CHUNK  1024
#define NCHUNK 49     // ceil(50000/1024)
#define NTILES 782    // ceil(50000/64)
#define GRID1  148    // persistent grid, occupancy 1
#define GRID2  296    // persistent grid, occupancy 2

// ---------------- scratch (device globals) -----------------------------------
__device__ int g_is64;
__device__ int g_cnt [NNODES];
__device__ int g_off [NNODES];
__device__ int g_cur [NNODES];
__device__ __align__(8) int g_src32[NEDGES];
__device__ __align__(8) int g_dst32[NEDGES];
__device__ int g_eidx [NEDGES];
__device__ int g_chunksum[64];
__device__ __align__(16) __half g_uh[NNODES * 128];  // x @ Wl1   (fp16)
__device__ __align__(16) __half g_vh[NNODES * 128];  // x @ Wr1   (fp16)
__device__ __align__(16) __half g_hh[NNODES * 128];  // layer1 out (fp16)
__device__ __align__(16) __half g_ph[NNODES * 64];   // h @ Wl2   (fp16)
__device__ __align__(16) float  g_q [NNODES * 64];   // h @ Wr2 + bl2

// ---------------- f32x2 / half helpers ----------------------------------------
typedef unsigned long long ull;
__device__ __forceinline__ ull pk2(float x, float y) {
    ull r; asm("mov.b64 %0, {%1, %2};" : "=l"(r) : "f"(x), "f"(y)); return r;
}
__device__ __forceinline__ ull pkdup(float x) {
    ull r; asm("mov.b64 %0, {%1, %1};" : "=l"(r) : "f"(x)); return r;
}
__device__ __forceinline__ void ffma2(ull& d, ull a, ull b) {
    asm("fma.rn.f32x2 %0, %1, %2, %0;" : "+l"(d) : "l"(a), "l"(b));
}
__device__ __forceinline__ float2 unpk(ull v) {
    float2 r; asm("mov.b64 {%0, %1}, %2;" : "=f"(r.x), "=f"(r.y) : "l"(v)); return r;
}
__device__ __forceinline__ unsigned h2u(__half2 h) {
    unsigned u; asm("mov.b32 %0, %1;" : "=r"(u) : "r"(*(unsigned*)&h)); return u;
}
__device__ __forceinline__ float2 u2f(unsigned u) {
    return __half22float2(*(__half2*)&u);
}

// ---------------- init: zero counts + dtype detect ---------------------------
__global__ void init_kernel(const int* __restrict__ ei32) {
    int i = blockIdx.x * blockDim.x + threadIdx.x;
    if (i < NNODES) g_cnt[i] = 0;
    if (i == 0) {
        int allzero = 1;
        #pragma unroll
        for (int j = 0; j < 64; j++)
            if (ei32[2 * j + 1] != 0) allzero = 0;
        g_is64 = allzero;
    }
}

// ---------------- hist: 2 edges per thread -----------------------------------
__global__ void hist_kernel(const void* __restrict__ ei) {
    int t = blockIdx.x * blockDim.x + threadIdx.x;
    int e = t * 2;
    if (e >= NEDGES) return;
    int s0, s1, d0, d1;
    if (g_is64) {
        const long long* e64 = (const long long*)ei;
        longlong2 ss = *(const longlong2*)(e64 + e);
        longlong2 dd = *(const longlong2*)(e64 + NEDGES + e);
        s0 = (int)ss.x; s1 = (int)ss.y; d0 = (int)dd.x; d1 = (int)dd.y;
    } else {
        const int* e32 = (const int*)ei;
        int2 ss = *(const int2*)(e32 + e);
        int2 dd = *(const int2*)(e32 + NEDGES + e);
        s0 = ss.x; s1 = ss.y; d0 = dd.x; d1 = dd.y;
    }
    s0 = min(max(s0, 0), NNODES - 1); s1 = min(max(s1, 0), NNODES - 1);
    d0 = min(max(d0, 0), NNODES - 1); d1 = min(max(d1, 0), NNODES - 1);
    *(int2*)(g_src32 + e) = make_int2(s0, s1);
    *(int2*)(g_dst32 + e) = make_int2(d0, d1);
    atomicAdd(&g_cnt[d0], 1);
    atomicAdd(&g_cnt[d1], 1);
}

// ---------------- scan phase 1: per-chunk sums --------------------------------
__global__ void scan_p1_kernel() {
    __shared__ int sm[CHUNK];
    int tid = threadIdx.x;
    int idx = blockIdx.x * CHUNK + tid;
    sm[tid] = (idx < NNODES) ? g_cnt[idx] : 0;
    __syncthreads();
    #pragma unroll
    for (int s = CHUNK / 2; s > 0; s >>= 1) {
        if (tid < s) sm[tid] += sm[tid + s];
        __syncthreads();
    }
    if (tid == 0) g_chunksum[blockIdx.x] = sm[0];
}

// ---------------- scan phase 2+3 merged ---------------------------------------
__global__ void scan_p23_kernel() {
    __shared__ int sums[64];
    __shared__ int sm[CHUNK];
    int tid = threadIdx.x;
    if (tid < 64) sums[tid] = (tid < NCHUNK) ? g_chunksum[tid] : 0;
    __syncthreads();
    if (tid == 0) {
        int run = 0;
        for (int i = 0; i < NCHUNK; i++) { int v = sums[i]; sums[i] = run; run += v; }
    }
    __syncthreads();
    int chunkoff = sums[blockIdx.x];

    int idx = blockIdx.x * CHUNK + tid;
    int v = (idx < NNODES) ? g_cnt[idx] : 0;
    sm[tid] = v;
    __syncthreads();
    #pragma unroll
    for (int d = 1; d < CHUNK; d <<= 1) {
        int t = (tid >= d) ? sm[tid - d] : 0;
        __syncthreads();
        sm[tid] += t;
        __syncthreads();
    }
    if (idx < NNODES) {
        int off = chunkoff + sm[tid] - v;   // exclusive
        g_off[idx] = off;
        g_cur[idx] = off;
    }
}

// ---------------- bucket fill: 2 edges per thread -----------------------------
__global__ void fill_kernel() {
    int t = blockIdx.x * blockDim.x + threadIdx.x;
    int e = t * 2;
    if (e >= NEDGES) return;
    int2 dd = *(const int2*)(g_dst32 + e);
    int2 ss = *(const int2*)(g_src32 + e);
    int pos0 = atomicAdd(&g_cur[dd.x], 1);
    if (pos0 >= 0 && pos0 < NEDGES) g_eidx[pos0] = ss.x;
    int pos1 = atomicAdd(&g_cur[dd.y], 1);
    if (pos1 >= 0 && pos1 < NEDGES) g_eidx[pos1] = ss.y;
}

// ---------------- GEMM X (persistent): u = x@Wl1 ; v = x@Wr1 (fp16 out) ------
// Tile 64x256, K=128. Grid=148, Ws loaded once, tiles looped.
// SMEM: Ws 128KB + As 32KB = 160KB.
__global__ void __launch_bounds__(256, 1)
gemmX_kernel(const float4* __restrict__ x4,
             const float4* __restrict__ Wl1,   // [128][32] f4
             const float4* __restrict__ Wr1) { // [128][32] f4
    extern __shared__ float sm[];
    float* Ws = sm;                 // [128][256]
    float* As = sm + 128 * 256;     // [128][64]  k-major
    int tid = threadIdx.x;
    int tx = tid & 31, ty = tid >> 5;

    float4* Ws4 = (float4*)Ws;
    #pragma unroll
    for (int i = tid; i < 8192; i += 256) {
        int k = i >> 6, c = i & 63;
        Ws4[i] = (c < 32) ? Wl1[k * 32 + c] : Wr1[k * 32 + (c - 32)];
    }

    uint2* uh2 = (uint2*)g_uh;
    uint2* vh2 = (uint2*)g_vh;

    for (int tile = blockIdx.x; tile < NTILES; tile += GRID1) {
        int m0 = tile * 64;
        __syncthreads();   // As reuse: prior FMA reads done
        #pragma unroll
        for (int i = tid; i < 2048; i += 256) {
            int r = i & 63, c = i >> 6;   // c 0..31
            int m = m0 + r;
            float4 v = (m < NNODES) ? x4[m * 32 + c] : make_float4(0.f, 0.f, 0.f, 0.f);
            As[(4 * c + 0) * 64 + r] = v.x;
            As[(4 * c + 1) * 64 + r] = v.y;
            As[(4 * c + 2) * 64 + r] = v.z;
            As[(4 * c + 3) * 64 + r] = v.w;
        }
        __syncthreads();

        ull acc[4][8] = {};   // [m-pair][n: 0..3 u, 4..7 v]
        #pragma unroll 4
        for (int k = 0; k < 128; k++) {
            const float* arow = As + k * 64 + ty * 8;
            float4 a0 = *(const float4*)arow;
            float4 a1 = *(const float4*)(arow + 4);
            ull ap[4];
            ap[0] = pk2(a0.x, a0.y); ap[1] = pk2(a0.z, a0.w);
            ap[2] = pk2(a1.x, a1.y); ap[3] = pk2(a1.z, a1.w);
            float4 bu = Ws4[k * 64 + tx];
            float4 bv = Ws4[k * 64 + 32 + tx];
            ull bd[8];
            bd[0] = pkdup(bu.x); bd[1] = pkdup(bu.y); bd[2] = pkdup(bu.z); bd[3] = pkdup(bu.w);
            bd[4] = pkdup(bv.x); bd[5] = pkdup(bv.y); bd[6] = pkdup(bv.z); bd[7] = pkdup(bv.w);
            #pragma unroll
            for (int ip = 0; ip < 4; ip++) {
                #pragma unroll
                for (int j = 0; j < 8; j++) ffma2(acc[ip][j], ap[ip], bd[j]);
            }
        }

        #pragma unroll
        for (int ip = 0; ip < 4; ip++) {
            float2 c0 = unpk(acc[ip][0]), c1 = unpk(acc[ip][1]);
            float2 c2 = unpk(acc[ip][2]), c3 = unpk(acc[ip][3]);
            float2 c4 = unpk(acc[ip][4]), c5 = unpk(acc[ip][5]);
            float2 c6 = unpk(acc[ip][6]), c7 = unpk(acc[ip][7]);
            int m = m0 + ty * 8 + 2 * ip;
            if (m < NNODES) {
                uint2 pu, pv;
                pu.x = h2u(__floats2half2_rn(c0.x, c1.x));
                pu.y = h2u(__floats2half2_rn(c2.x, c3.x));
                pv.x = h2u(__floats2half2_rn(c4.x, c5.x));
                pv.y = h2u(__floats2half2_rn(c6.x, c7.x));
                uh2[m * 32 + tx] = pu;
                vh2[m * 32 + tx] = pv;
            }
            if (m + 1 < NNODES) {
                uint2 pu, pv;
                pu.x = h2u(__floats2half2_rn(c0.y, c1.y));
                pu.y = h2u(__floats2half2_rn(c2.y, c3.y));
                pv.x = h2u(__floats2half2_rn(c4.y, c5.y));
                pv.y = h2u(__floats2half2_rn(c6.y, c7.y));
                uh2[(m + 1) * 32 + tx] = pu;
                vh2[(m + 1) * 32 + tx] = pv;
            }
        }
    }
}

// ---------------- gatherH: h = relu(mean_agg(u_fp16) + bl1 + v_fp16) ---------
__global__ void gatherH_kernel(const float4* __restrict__ bl1) {
    int w    = (blockIdx.x * blockDim.x + threadIdx.x) >> 5;
    int lane = threadIdx.x & 31;
    if (w >= NNODES) return;
    int beg = g_off[w];
    int c   = g_cnt[w];
    const uint2* uh2 = (const uint2*)g_uh;
    float4 acc = make_float4(0.f, 0.f, 0.f, 0.f);
    int i = 0;
    for (; i + 3 < c; i += 4) {
        int s0 = g_eidx[beg + i];
        int s1 = g_eidx[beg + i + 1];
        int s2 = g_eidx[beg + i + 2];
        int s3 = g_eidx[beg + i + 3];
        uint2 r0 = uh2[s0 * 32 + lane];
        uint2 r1 = uh2[s1 * 32 + lane];
        uint2 r2 = uh2[s2 * 32 + lane];
        uint2 r3 = uh2[s3 * 32 + lane];
        float2 f;
        f = u2f(r0.x); acc.x += f.x; acc.y += f.y;
        f = u2f(r0.y); acc.z += f.x; acc.w += f.y;
        f = u2f(r1.x); acc.x += f.x; acc.y += f.y;
        f = u2f(r1.y); acc.z += f.x; acc.w += f.y;
        f = u2f(r2.x); acc.x += f.x; acc.y += f.y;
        f = u2f(r2.y); acc.z += f.x; acc.w += f.y;
        f = u2f(r3.x); acc.x += f.x; acc.y += f.y;
        f = u2f(r3.y); acc.z += f.x; acc.w += f.y;
    }
    for (; i < c; i++) {
        int s0 = g_eidx[beg + i];
        uint2 r0 = uh2[s0 * 32 + lane];
        float2 f;
        f = u2f(r0.x); acc.x += f.x; acc.y += f.y;
        f = u2f(r0.y); acc.z += f.x; acc.w += f.y;
    }
    float rd = 1.0f / (float)max(c, 1);
    float4 b = bl1[lane];
    uint2 rv = ((const uint2*)g_vh)[w * 32 + lane];
    float2 v01 = u2f(rv.x), v23 = u2f(rv.y);
    float o0 = fmaxf(acc.x * rd + b.x + v01.x, 0.f);
    float o1 = fmaxf(acc.y * rd + b.y + v01.y, 0.f);
    float o2 = fmaxf(acc.z * rd + b.z + v23.x, 0.f);
    float o3 = fmaxf(acc.w * rd + b.w + v23.y, 0.f);
    uint2 ph;
    ph.x = h2u(__floats2half2_rn(o0, o1));
    ph.y = h2u(__floats2half2_rn(o2, o3));
    ((uint2*)g_hh)[w * 32 + lane] = ph;
}

// ---------------- GEMM2 (persistent): p = h@Wl2 (fp16) ; q = h@Wr2 + bl2 -----
// Tile 64x128, K=128. Grid=296, occupancy 2. SMEM: Ws 64KB + As 32KB = 96KB.
__global__ void __launch_bounds__(256, 2)
gemm2_kernel(const float4* __restrict__ Wl2,   // [128][16] f4
             const float4* __restrict__ Wr2,   // [128][16] f4
             const float4* __restrict__ bl2) { // [16] f4
    extern __shared__ float sm[];
    float* Ws = sm;                 // [128][128]
    float* As = sm + 128 * 128;     // [128][64]  k-major
    int tid = threadIdx.x;
    int tx = tid & 31, ty = tid >> 5;

    float4* Ws4 = (float4*)Ws;
    #pragma unroll
    for (int i = tid; i < 4096; i += 256) {
        int k = i >> 5, c = i & 31;
        Ws4[i] = (c < 16) ? Wl2[k * 16 + c] : Wr2[k * 16 + (c - 16)];
    }

    const uint2* hh2 = (const uint2*)g_hh;
    uint2*  ph2 = (uint2*)g_ph;
    float4* q4  = (float4*)g_q;
    float4 bias = bl2[(tx >= 16) ? (tx - 16) : 0];

    for (int tile = blockIdx.x; tile < NTILES; tile += GRID2) {
        int m0 = tile * 64;
        __syncthreads();
        #pragma unroll
        for (int i = tid; i < 2048; i += 256) {
            int r = i & 63, c = i >> 6;   // c 0..31
            int m = m0 + r;
            float4 v = make_float4(0.f, 0.f, 0.f, 0.f);
            if (m < NNODES) {
                uint2 hv = hh2[m * 32 + c];
                float2 f01 = u2f(hv.x), f23 = u2f(hv.y);
                v = make_float4(f01.x, f01.y, f23.x, f23.y);
            }
            As[(4 * c + 0) * 64 + r] = v.x;
            As[(4 * c + 1) * 64 + r] = v.y;
            As[(4 * c + 2) * 64 + r] = v.z;
            As[(4 * c + 3) * 64 + r] = v.w;
        }
        __syncthreads();

        ull acc[4][4] = {};
        #pragma unroll 4
        for (int k = 0; k < 128; k++) {
            const float* arow = As + k * 64 + ty * 8;
            float4 a0 = *(const float4*)arow;
            float4 a1 = *(const float4*)(arow + 4);
            ull ap[4];
            ap[0] = pk2(a0.x, a0.y); ap[1] = pk2(a0.z, a0.w);
            ap[2] = pk2(a1.x, a1.y); ap[3] = pk2(a1.z, a1.w);
            float4 b = Ws4[k * 32 + tx];
            ull bd0 = pkdup(b.x), bd1 = pkdup(b.y), bd2 = pkdup(b.z), bd3 = pkdup(b.w);
            #pragma unroll
            for (int ip = 0; ip < 4; ip++) {
                ffma2(acc[ip][0], ap[ip], bd0);
                ffma2(acc[ip][1], ap[ip], bd1);
                ffma2(acc[ip][2], ap[ip], bd2);
                ffma2(acc[ip][3], ap[ip], bd3);
            }
        }

        if (tx < 16) {
            #pragma unroll
            for (int ip = 0; ip < 4; ip++) {
                float2 c0 = unpk(acc[ip][0]), c1 = unpk(acc[ip][1]);
                float2 c2 = unpk(acc[ip][2]), c3 = unpk(acc[ip][3]);
                int m = m0 + ty * 8 + 2 * ip;
                if (m < NNODES) {
                    uint2 pu;
                    pu.x = h2u(__floats2half2_rn(c0.x, c1.x));
                    pu.y = h2u(__floats2half2_rn(c2.x, c3.x));
                    ph2[m * 16 + tx] = pu;
                }
                if (m + 1 < NNODES) {
                    uint2 pu;
                    pu.x = h2u(__floats2half2_rn(c0.y, c1.y));
                    pu.y = h2u(__floats2half2_rn(c2.y, c3.y));
                    ph2[(m + 1) * 16 + tx] = pu;
                }
            }
        } else {
            #pragma unroll
            for (int ip = 0; ip < 4; ip++) {
                float2 c0 = unpk(acc[ip][0]), c1 = unpk(acc[ip][1]);
                float2 c2 = unpk(acc[ip][2]), c3 = unpk(acc[ip][3]);
                int m = m0 + ty * 8 + 2 * ip;
                if (m < NNODES)
                    q4[m * 16 + (tx - 16)] = make_float4(c0.x + bias.x, c1.x + bias.y,
                                                         c2.x + bias.z, c3.x + bias.w);
                if (m + 1 < NNODES)
                    q4[(m + 1) * 16 + (tx - 16)] = make_float4(c0.y + bias.x, c1.y + bias.y,
                                                               c2.y + bias.z, c3.y + bias.w);
            }
        }
    }
}

// ---------------- gather layer 2 (fp16 p) + log_softmax (fused) ---------------
__global__ void gather2_final_kernel(float* __restrict__ out) {
    int w    = (blockIdx.x * blockDim.x + threadIdx.x) >> 5;
    int lane = threadIdx.x & 31;
    if (w >= NNODES) return;
    int beg = g_off[w];
    int c   = g_cnt[w];
    const unsigned* ph = (const unsigned*)g_ph;   // half2 per entry, 32 per row
    float2 acc = make_float2(0.f, 0.f);
    int i = 0;
    for (; i + 3 < c; i += 4) {
        int s0 = g_eidx[beg + i];
        int s1 = g_eidx[beg + i + 1];
        int s2 = g_eidx[beg + i + 2];
        int s3 = g_eidx[beg + i + 3];
        unsigned r0 = ph[s0 * 32 + lane];
        unsigned r1 = ph[s1 * 32 + lane];
        unsigned r2 = ph[s2 * 32 + lane];
        unsigned r3 = ph[s3 * 32 + lane];
        float2 f;
        f = u2f(r0); acc.x += f.x; acc.y += f.y;
        f = u2f(r1); acc.x += f.x; acc.y += f.y;
        f = u2f(r2); acc.x += f.x; acc.y += f.y;
        f = u2f(r3); acc.x += f.x; acc.y += f.y;
    }
    for (; i < c; i++) {
        int s0 = g_eidx[beg + i];
        float2 f = u2f(ph[s0 * 32 + lane]);
        acc.x += f.x; acc.y += f.y;
    }
    float rd = 1.0f / (float)max(c, 1);
    float2 q = ((const float2*)g_q)[w * 32 + lane];
    float v0 = acc.x * rd + q.x;
    float v1 = acc.y * rd + q.y;

    float mx = fmaxf(v0, v1);
    #pragma unroll
    for (int o = 16; o; o >>= 1) mx = fmaxf(mx, __shfl_xor_sync(0xffffffffu, mx, o));
    float s = expf(v0 - mx) + expf(v1 - mx);
    #pragma unroll
    for (int o = 16; o; o >>= 1) s += __shfl_xor_sync(0xffffffffu, s, o);
    float ls = logf(s) + mx;

    ((float2*)out)[w * 32 + lane] = make_float2(v0 - ls, v1 - ls);
}

// ---------------- stream/event resources (created once, pre-checkpoint) ------
static cudaStream_t g_s2   = nullptr;
static cudaEvent_t  g_fork = nullptr;
static cudaEvent_t  g_join = nullptr;

static void ensure_resources() {
    if (!g_s2) {
        cudaStreamCreateWithFlags(&g_s2, cudaStreamNonBlocking);
        cudaEventCreateWithFlags(&g_fork, cudaEventDisableTiming);
        cudaEventCreateWithFlags(&g_join, cudaEventDisableTiming);
    }
}
namespace { struct ResInit { ResInit() { ensure_resources(); } } g_resinit; }

// ---------------- launch ------------------------------------------------------
extern "C" void kernel_launch(void* const* d_in, const int* in_sizes, int n_in,
                              void* d_out, int out_size) {
    const float4* x4   = (const float4*)d_in[0];
    const void*   ei   = d_in[1];
    const float4* Wl1  = (const float4*)d_in[2];
    const float4* bl1  = (const float4*)d_in[3];
    const float4* Wr1  = (const float4*)d_in[4];
    const float4* Wl2  = (const float4*)d_in[5];
    const float4* bl2  = (const float4*)d_in[6];
    const float4* Wr2  = (const float4*)d_in[7];
    float*        out  = (float*)d_out;

    ensure_resources();
    cudaFuncSetAttribute(gemmX_kernel, cudaFuncAttributeMaxDynamicSharedMemorySize, 163840);
    cudaFuncSetAttribute(gemm2_kernel, cudaFuncAttributeMaxDynamicSharedMemorySize, 98304);

    // ---- fork: CSR build on g_s2, concurrent with gemmX on the main stream ----
    cudaEventRecord(g_fork, 0);
    cudaStreamWaitEvent(g_s2, g_fork, 0);

    init_kernel<<<(NNODES + 255) / 256, 256, 0, g_s2>>>((const int*)ei);
    hist_kernel<<<(NEDGES / 2 + 255) / 256, 256, 0, g_s2>>>(ei);
    scan_p1_kernel<<<NCHUNK, CHUNK, 0, g_s2>>>();
    scan_p23_kernel<<<NCHUNK, CHUNK, 0, g_s2>>>();
    fill_kernel<<<(NEDGES / 2 + 255) / 256, 256, 0, g_s2>>>();
    cudaEventRecord(g_join, g_s2);

    gemmX_kernel<<<GRID1, 256, 163840>>>(x4, Wl1, Wr1);

    // ---- join ----
    cudaStreamWaitEvent(0, g_join, 0);

    gatherH_kernel<<<(NNODES * 32 + 255) / 256, 256>>>(bl1);
    gemm2_kernel<<<GRID2, 256, 98304>>>(Wl2, Wr2, bl2);
    gather2_final_kernel<<<(NNODES * 32 + 255) / 256, 256>>>(out);
}

// round 12
// speedup vs baseline: 1.6116x; 1.4188x over previous
#include <cuda_runtime.h>
#include <cuda_bf16.h>
#include <cuda_fp16.h>

#define NNODES 50000
#define NEDGES 600000
#define CHUNK  1024
#define NCHUNK 49     // ceil(50000/1024)
#define NTILES 782    // ceil(50000/64)
#define GRIDX  296    // persistent grid (occupancy 2)
#define GRID2  296

// smem strides (halves), padded for ldmatrix bank behavior; multiples of 8
#define ASTR 136
#define BSTRX 264     // gemmX Bs: [128][256] +8 pad
#define BSTR2 136     // gemm2 Bs: [128][128] +8 pad
#define GX_SMEM (128*BSTRX*2 + 64*ASTR*2)   // 84992
#define G2_SMEM (128*BSTR2*2 + 64*ASTR*2)   // 52224

// ---------------- scratch (device globals) -----------------------------------
__device__ int g_is64;
__device__ int g_cnt [NNODES];
__device__ int g_off [NNODES];
__device__ int g_cur [NNODES];
__device__ __align__(8) int g_src32[NEDGES];
__device__ __align__(8) int g_dst32[NEDGES];
__device__ int g_eidx [NEDGES];
__device__ int g_chunksum[64];
__device__ __align__(16) __half g_uh[NNODES * 128];  // x @ Wl1   (fp16)
__device__ __align__(16) __half g_vh[NNODES * 128];  // x @ Wr1   (fp16)
__device__ __align__(16) __half g_hh[NNODES * 128];  // layer1 out (fp16)
__device__ __align__(16) __half g_ph[NNODES * 64];   // h @ Wl2   (fp16)
__device__ __align__(16) float  g_q [NNODES * 64];   // h @ Wr2 + bl2

// ---------------- helpers -------------------------------------------------------
__device__ __forceinline__ unsigned h2u(__half2 h) {
    unsigned u; asm("mov.b32 %0, %1;" : "=r"(u) : "r"(*(unsigned*)&h)); return u;
}
__device__ __forceinline__ float2 u2f(unsigned u) {
    return __half22float2(*(__half2*)&u);
}
__device__ __forceinline__ void ldsm_x4(unsigned& r0, unsigned& r1, unsigned& r2, unsigned& r3, unsigned addr) {
    asm volatile("ldmatrix.sync.aligned.m8n8.x4.shared.b16 {%0,%1,%2,%3}, [%4];"
                 : "=r"(r0), "=r"(r1), "=r"(r2), "=r"(r3) : "r"(addr));
}
__device__ __forceinline__ void ldsm_x4t(unsigned& r0, unsigned& r1, unsigned& r2, unsigned& r3, unsigned addr) {
    asm volatile("ldmatrix.sync.aligned.m8n8.x4.trans.shared.b16 {%0,%1,%2,%3}, [%4];"
                 : "=r"(r0), "=r"(r1), "=r"(r2), "=r"(r3) : "r"(addr));
}
__device__ __forceinline__ void mma16816(float* d, unsigned a0, unsigned a1, unsigned a2, unsigned a3,
                                         unsigned b0, unsigned b1) {
    asm volatile("mma.sync.aligned.m16n8k16.row.col.f32.f16.f16.f32 "
                 "{%0,%1,%2,%3}, {%4,%5,%6,%7}, {%8,%9}, {%0,%1,%2,%3};"
                 : "+f"(d[0]), "+f"(d[1]), "+f"(d[2]), "+f"(d[3])
                 : "r"(a0), "r"(a1), "r"(a2), "r"(a3), "r"(b0), "r"(b1));
}

// ---------------- init: zero counts + dtype detect ---------------------------
__global__ void init_kernel(const int* __restrict__ ei32) {
    int i = blockIdx.x * blockDim.x + threadIdx.x;
    if (i < NNODES) g_cnt[i] = 0;
    if (i == 0) {
        int allzero = 1;
        #pragma unroll
        for (int j = 0; j < 64; j++)
            if (ei32[2 * j + 1] != 0) allzero = 0;
        g_is64 = allzero;
    }
}

// ---------------- hist: 2 edges per thread -----------------------------------
__global__ void hist_kernel(const void* __restrict__ ei) {
    int t = blockIdx.x * blockDim.x + threadIdx.x;
    int e = t * 2;
    if (e >= NEDGES) return;
    int s0, s1, d0, d1;
    if (g_is64) {
        const long long* e64 = (const long long*)ei;
        longlong2 ss = *(const longlong2*)(e64 + e);
        longlong2 dd = *(const longlong2*)(e64 + NEDGES + e);
        s0 = (int)ss.x; s1 = (int)ss.y; d0 = (int)dd.x; d1 = (int)dd.y;
    } else {
        const int* e32 = (const int*)ei;
        int2 ss = *(const int2*)(e32 + e);
        int2 dd = *(const int2*)(e32 + NEDGES + e);
        s0 = ss.x; s1 = ss.y; d0 = dd.x; d1 = dd.y;
    }
    s0 = min(max(s0, 0), NNODES - 1); s1 = min(max(s1, 0), NNODES - 1);
    d0 = min(max(d0, 0), NNODES - 1); d1 = min(max(d1, 0), NNODES - 1);
    *(int2*)(g_src32 + e) = make_int2(s0, s1);
    *(int2*)(g_dst32 + e) = make_int2(d0, d1);
    atomicAdd(&g_cnt[d0], 1);
    atomicAdd(&g_cnt[d1], 1);
}

// ---------------- scan phase 1 -------------------------------------------------
__global__ void scan_p1_kernel() {
    __shared__ int sm[CHUNK];
    int tid = threadIdx.x;
    int idx = blockIdx.x * CHUNK + tid;
    sm[tid] = (idx < NNODES) ? g_cnt[idx] : 0;
    __syncthreads();
    #pragma unroll
    for (int s = CHUNK / 2; s > 0; s >>= 1) {
        if (tid < s) sm[tid] += sm[tid + s];
        __syncthreads();
    }
    if (tid == 0) g_chunksum[blockIdx.x] = sm[0];
}

// ---------------- scan phase 2+3 merged ---------------------------------------
__global__ void scan_p23_kernel() {
    __shared__ int sums[64];
    __shared__ int sm[CHUNK];
    int tid = threadIdx.x;
    if (tid < 64) sums[tid] = (tid < NCHUNK) ? g_chunksum[tid] : 0;
    __syncthreads();
    if (tid == 0) {
        int run = 0;
        for (int i = 0; i < NCHUNK; i++) { int v = sums[i]; sums[i] = run; run += v; }
    }
    __syncthreads();
    int chunkoff = sums[blockIdx.x];

    int idx = blockIdx.x * CHUNK + tid;
    int v = (idx < NNODES) ? g_cnt[idx] : 0;
    sm[tid] = v;
    __syncthreads();
    #pragma unroll
    for (int d = 1; d < CHUNK; d <<= 1) {
        int t = (tid >= d) ? sm[tid - d] : 0;
        __syncthreads();
        sm[tid] += t;
        __syncthreads();
    }
    if (idx < NNODES) {
        int off = chunkoff + sm[tid] - v;   // exclusive
        g_off[idx] = off;
        g_cur[idx] = off;
    }
}

// ---------------- bucket fill ---------------------------------------------------
__global__ void fill_kernel() {
    int t = blockIdx.x * blockDim.x + threadIdx.x;
    int e = t * 2;
    if (e >= NEDGES) return;
    int2 dd = *(const int2*)(g_dst32 + e);
    int2 ss = *(const int2*)(g_src32 + e);
    int pos0 = atomicAdd(&g_cur[dd.x], 1);
    if (pos0 >= 0 && pos0 < NEDGES) g_eidx[pos0] = ss.x;
    int pos1 = atomicAdd(&g_cur[dd.y], 1);
    if (pos1 >= 0 && pos1 < NEDGES) g_eidx[pos1] = ss.y;
}

// ---------------- GEMM X (persistent, HMMA): u = x@Wl1 ; v = x@Wr1 ------------
// Block tile 64x256, K=128. 8 warps: warp = (m-quad 16 rows) x (n-half 128 cols).
__global__ void __launch_bounds__(256, 2)
gemmX_kernel(const float4* __restrict__ x4,
             const float4* __restrict__ Wl1,   // [128][32] f4
             const float4* __restrict__ Wr1) { // [128][32] f4
    extern __shared__ __half smh[];
    __half* Bs = smh;                 // [128][BSTRX]
    __half* As = smh + 128 * BSTRX;   // [64][ASTR]
    int tid = threadIdx.x;
    int w = tid >> 5, l = tid & 31;

    // load weights fp32 -> fp16 once
    for (int i = tid; i < 8192; i += 256) {
        int k = i >> 6, c = i & 63;
        float4 wv = (c < 32) ? Wl1[k * 32 + c] : Wr1[k * 32 + (c - 32)];
        uint2 pu;
        pu.x = h2u(__floats2half2_rn(wv.x, wv.y));
        pu.y = h2u(__floats2half2_rn(wv.z, wv.w));
        *(uint2*)(Bs + k * BSTRX + c * 4) = pu;
    }

    unsigned As_u32 = (unsigned)__cvta_generic_to_shared(As);
    unsigned Bs_u32 = (unsigned)__cvta_generic_to_shared(Bs);
    int wm = (w & 3) * 16;
    int nh = w >> 2;                    // 0 -> u, 1 -> v
    unsigned* dest = nh ? (unsigned*)g_vh : (unsigned*)g_uh;

    int rl = (l & 7) + (l & 8);         // 0..15
    int co = (l & 16) >> 1;             // 0 or 8
    unsigned a_base = As_u32 + ((wm + rl) * ASTR + co) * 2;
    unsigned b_base = Bs_u32 + (rl * BSTRX + nh * 128 + co) * 2;

    int g  = l >> 2;
    int t2 = (l & 3) * 2;

    for (int tile = blockIdx.x; tile < NTILES; tile += GRIDX) {
        int m0 = tile * 64;
        __syncthreads();
        for (int i = tid; i < 2048; i += 256) {
            int r = i & 63, c = i >> 6;   // c 0..31
            int m = m0 + r;
            float4 v = (m < NNODES) ? x4[m * 32 + c] : make_float4(0.f, 0.f, 0.f, 0.f);
            uint2 pu;
            pu.x = h2u(__floats2half2_rn(v.x, v.y));
            pu.y = h2u(__floats2half2_rn(v.z, v.w));
            *(uint2*)(As + r * ASTR + c * 4) = pu;
        }
        __syncthreads();

        float acc[16][4];
        #pragma unroll
        for (int j = 0; j < 16; j++)
            #pragma unroll
            for (int q = 0; q < 4; q++) acc[j][q] = 0.f;

        #pragma unroll
        for (int ks = 0; ks < 8; ks++) {
            int k0 = ks * 16;
            unsigned a0, a1, a2, a3;
            ldsm_x4(a0, a1, a2, a3, a_base + k0 * 2);
            #pragma unroll
            for (int jn = 0; jn < 8; jn++) {
                unsigned b0, b1, b2, b3;
                ldsm_x4t(b0, b1, b2, b3, b_base + (k0 * BSTRX + jn * 16) * 2);
                mma16816(acc[2 * jn],     a0, a1, a2, a3, b0, b1);
                mma16816(acc[2 * jn + 1], a0, a1, a2, a3, b2, b3);
            }
        }

        int row0 = m0 + wm + g;
        int row1 = row0 + 8;
        #pragma unroll
        for (int j = 0; j < 16; j++) {
            int uidx = j * 4 + (t2 >> 1);   // (j*8 + t2)/2
            if (row0 < NNODES) dest[row0 * 64 + uidx] = h2u(__floats2half2_rn(acc[j][0], acc[j][1]));
            if (row1 < NNODES) dest[row1 * 64 + uidx] = h2u(__floats2half2_rn(acc[j][2], acc[j][3]));
        }
    }
}

// ---------------- gatherH: h = relu(mean_agg(u_fp16) + bl1 + v_fp16) ---------
__global__ void gatherH_kernel(const float4* __restrict__ bl1) {
    int w    = (blockIdx.x * blockDim.x + threadIdx.x) >> 5;
    int lane = threadIdx.x & 31;
    if (w >= NNODES) return;
    int beg = g_off[w];
    int c   = g_cnt[w];
    const uint2* uh2 = (const uint2*)g_uh;
    float4 acc = make_float4(0.f, 0.f, 0.f, 0.f);
    int i = 0;
    for (; i + 3 < c; i += 4) {
        int s0 = g_eidx[beg + i];
        int s1 = g_eidx[beg + i + 1];
        int s2 = g_eidx[beg + i + 2];
        int s3 = g_eidx[beg + i + 3];
        uint2 r0 = uh2[s0 * 32 + lane];
        uint2 r1 = uh2[s1 * 32 + lane];
        uint2 r2 = uh2[s2 * 32 + lane];
        uint2 r3 = uh2[s3 * 32 + lane];
        float2 f;
        f = u2f(r0.x); acc.x += f.x; acc.y += f.y;
        f = u2f(r0.y); acc.z += f.x; acc.w += f.y;
        f = u2f(r1.x); acc.x += f.x; acc.y += f.y;
        f = u2f(r1.y); acc.z += f.x; acc.w += f.y;
        f = u2f(r2.x); acc.x += f.x; acc.y += f.y;
        f = u2f(r2.y); acc.z += f.x; acc.w += f.y;
        f = u2f(r3.x); acc.x += f.x; acc.y += f.y;
        f = u2f(r3.y); acc.z += f.x; acc.w += f.y;
    }
    for (; i < c; i++) {
        int s0 = g_eidx[beg + i];
        uint2 r0 = uh2[s0 * 32 + lane];
        float2 f;
        f = u2f(r0.x); acc.x += f.x; acc.y += f.y;
        f = u2f(r0.y); acc.z += f.x; acc.w += f.y;
    }
    float rd = 1.0f / (float)max(c, 1);
    float4 b = bl1[lane];
    uint2 rv = ((const uint2*)g_vh)[w * 32 + lane];
    float2 v01 = u2f(rv.x), v23 = u2f(rv.y);
    float o0 = fmaxf(acc.x * rd + b.x + v01.x, 0.f);
    float o1 = fmaxf(acc.y * rd + b.y + v01.y, 0.f);
    float o2 = fmaxf(acc.z * rd + b.z + v23.x, 0.f);
    float o3 = fmaxf(acc.w * rd + b.w + v23.y, 0.f);
    uint2 ph;
    ph.x = h2u(__floats2half2_rn(o0, o1));
    ph.y = h2u(__floats2half2_rn(o2, o3));
    ((uint2*)g_hh)[w * 32 + lane] = ph;
}

// ---------------- GEMM2 (persistent, HMMA): p = h@Wl2 ; q = h@Wr2 + bl2 ------
// Block tile 64x128, K=128. 8 warps: (m-quad 16 rows) x (n-half 64 cols).
__global__ void __launch_bounds__(256, 2)
gemm2_kernel(const float4* __restrict__ Wl2,   // [128][16] f4
             const float4* __restrict__ Wr2,   // [128][16] f4
             const float4* __restrict__ bl2) { // [16] f4
    extern __shared__ __half smh[];
    __half* Bs = smh;                 // [128][BSTR2]
    __half* As = smh + 128 * BSTR2;   // [64][ASTR]
    int tid = threadIdx.x;
    int w = tid >> 5, l = tid & 31;
    const float* bl2f = (const float*)bl2;

    for (int i = tid; i < 4096; i += 256) {
        int k = i >> 5, c = i & 31;
        float4 wv = (c < 16) ? Wl2[k * 16 + c] : Wr2[k * 16 + (c - 16)];
        uint2 pu;
        pu.x = h2u(__floats2half2_rn(wv.x, wv.y));
        pu.y = h2u(__floats2half2_rn(wv.z, wv.w));
        *(uint2*)(Bs + k * BSTR2 + c * 4) = pu;
    }

    unsigned As_u32 = (unsigned)__cvta_generic_to_shared(As);
    unsigned Bs_u32 = (unsigned)__cvta_generic_to_shared(Bs);
    int wm = (w & 3) * 16;
    int nh = w >> 2;                    // 0 -> p (fp16), 1 -> q (fp32+bias)

    int rl = (l & 7) + (l & 8);
    int co = (l & 16) >> 1;
    unsigned a_base = As_u32 + ((wm + rl) * ASTR + co) * 2;
    unsigned b_base = Bs_u32 + (rl * BSTR2 + nh * 64 + co) * 2;

    int g  = l >> 2;
    int t2 = (l & 3) * 2;

    const uint2* hh2 = (const uint2*)g_hh;
    unsigned* ph = (unsigned*)g_ph;
    float2*   q2 = (float2*)g_q;

    for (int tile = blockIdx.x; tile < NTILES; tile += GRID2) {
        int m0 = tile * 64;
        __syncthreads();
        for (int i = tid; i < 2048; i += 256) {
            int r = i & 63, c = i >> 6;   // c 0..31
            int m = m0 + r;
            uint2 hv = (m < NNODES) ? hh2[m * 32 + c] : make_uint2(0u, 0u);
            *(uint2*)(As + r * ASTR + c * 4) = hv;
        }
        __syncthreads();

        float acc[8][4];
        #pragma unroll
        for (int j = 0; j < 8; j++)
            #pragma unroll
            for (int q = 0; q < 4; q++) acc[j][q] = 0.f;

        #pragma unroll
        for (int ks = 0; ks < 8; ks++) {
            int k0 = ks * 16;
            unsigned a0, a1, a2, a3;
            ldsm_x4(a0, a1, a2, a3, a_base + k0 * 2);
            #pragma unroll
            for (int jn = 0; jn < 4; jn++) {
                unsigned b0, b1, b2, b3;
                ldsm_x4t(b0, b1, b2, b3, b_base + (k0 * BSTR2 + jn * 16) * 2);
                mma16816(acc[2 * jn],     a0, a1, a2, a3, b0, b1);
                mma16816(acc[2 * jn + 1], a0, a1, a2, a3, b2, b3);
            }
        }

        int row0 = m0 + wm + g;
        int row1 = row0 + 8;
        if (nh == 0) {
            #pragma unroll
            for (int j = 0; j < 8; j++) {
                int uidx = j * 4 + (t2 >> 1);   // (j*8+t2)/2, 64-col row -> 32 u32
                if (row0 < NNODES) ph[row0 * 32 + uidx] = h2u(__floats2half2_rn(acc[j][0], acc[j][1]));
                if (row1 < NNODES) ph[row1 * 32 + uidx] = h2u(__floats2half2_rn(acc[j][2], acc[j][3]));
            }
        } else {
            #pragma unroll
            for (int j = 0; j < 8; j++) {
                int col = j * 8 + t2;           // 0..63
                float b0 = bl2f[col], b1 = bl2f[col + 1];
                int uidx = j * 4 + (t2 >> 1);
                if (row0 < NNODES) q2[row0 * 32 + uidx] = make_float2(acc[j][0] + b0, acc[j][1] + b1);
                if (row1 < NNODES) q2[row1 * 32 + uidx] = make_float2(acc[j][2] + b0, acc[j][3] + b1);
            }
        }
    }
}

// ---------------- gather layer 2 (fp16 p) + log_softmax (fused) ---------------
__global__ void gather2_final_kernel(float* __restrict__ out) {
    int w    = (blockIdx.x * blockDim.x + threadIdx.x) >> 5;
    int lane = threadIdx.x & 31;
    if (w >= NNODES) return;
    int beg = g_off[w];
    int c   = g_cnt[w];
    const unsigned* ph = (const unsigned*)g_ph;
    float2 acc = make_float2(0.f, 0.f);
    int i = 0;
    for (; i + 3 < c; i += 4) {
        int s0 = g_eidx[beg + i];
        int s1 = g_eidx[beg + i + 1];
        int s2 = g_eidx[beg + i + 2];
        int s3 = g_eidx[beg + i + 3];
        unsigned r0 = ph[s0 * 32 + lane];
        unsigned r1 = ph[s1 * 32 + lane];
        unsigned r2 = ph[s2 * 32 + lane];
        unsigned r3 = ph[s3 * 32 + lane];
        float2 f;
        f = u2f(r0); acc.x += f.x; acc.y += f.y;
        f = u2f(r1); acc.x += f.x; acc.y += f.y;
        f = u2f(r2); acc.x += f.x; acc.y += f.y;
        f = u2f(r3); acc.x += f.x; acc.y += f.y;
    }
    for (; i < c; i++) {
        int s0 = g_eidx[beg + i];
        float2 f = u2f(ph[s0 * 32 + lane]);
        acc.x += f.x; acc.y += f.y;
    }
    float rd = 1.0f / (float)max(c, 1);
    float2 q = ((const float2*)g_q)[w * 32 + lane];
    float v0 = acc.x * rd + q.x;
    float v1 = acc.y * rd + q.y;

    float mx = fmaxf(v0, v1);
    #pragma unroll
    for (int o = 16; o; o >>= 1) mx = fmaxf(mx, __shfl_xor_sync(0xffffffffu, mx, o));
    float s = expf(v0 - mx) + expf(v1 - mx);
    #pragma unroll
    for (int o = 16; o; o >>= 1) s += __shfl_xor_sync(0xffffffffu, s, o);
    float ls = logf(s) + mx;

    ((float2*)out)[w * 32 + lane] = make_float2(v0 - ls, v1 - ls);
}

// ---------------- stream/event resources (created once, pre-checkpoint) ------
static cudaStream_t g_s2   = nullptr;
static cudaEvent_t  g_fork = nullptr;
static cudaEvent_t  g_join = nullptr;

static void ensure_resources() {
    if (!g_s2) {
        cudaStreamCreateWithFlags(&g_s2, cudaStreamNonBlocking);
        cudaEventCreateWithFlags(&g_fork, cudaEventDisableTiming);
        cudaEventCreateWithFlags(&g_join, cudaEventDisableTiming);
    }
}
namespace { struct ResInit { ResInit() { ensure_resources(); } } g_resinit; }

// ---------------- launch ------------------------------------------------------
extern "C" void kernel_launch(void* const* d_in, const int* in_sizes, int n_in,
                              void* d_out, int out_size) {
    const float4* x4   = (const float4*)d_in[0];
    const void*   ei   = d_in[1];
    const float4* Wl1  = (const float4*)d_in[2];
    const float4* bl1  = (const float4*)d_in[3];
    const float4* Wr1  = (const float4*)d_in[4];
    const float4* Wl2  = (const float4*)d_in[5];
    const float4* bl2  = (const float4*)d_in[6];
    const float4* Wr2  = (const float4*)d_in[7];
    float*        out  = (float*)d_out;

    ensure_resources();
    cudaFuncSetAttribute(gemmX_kernel, cudaFuncAttributeMaxDynamicSharedMemorySize, GX_SMEM);
    cudaFuncSetAttribute(gemm2_kernel, cudaFuncAttributeMaxDynamicSharedMemorySize, G2_SMEM);

    // ---- fork: CSR build on g_s2, concurrent with gemmX on the main stream ----
    cudaEventRecord(g_fork, 0);
    cudaStreamWaitEvent(g_s2, g_fork, 0);

    init_kernel<<<(NNODES + 255) / 256, 256, 0, g_s2>>>((const int*)ei);
    hist_kernel<<<(NEDGES / 2 + 255) / 256, 256, 0, g_s2>>>(ei);
    scan_p1_kernel<<<NCHUNK, CHUNK, 0, g_s2>>>();
    scan_p23_kernel<<<NCHUNK, CHUNK, 0, g_s2>>>();
    fill_kernel<<<(NEDGES / 2 + 255) / 256, 256, 0, g_s2>>>();
    cudaEventRecord(g_join, g_s2);

    gemmX_kernel<<<GRIDX, 256, GX_SMEM>>>(x4, Wl1, Wr1);

    // ---- join ----
    cudaStreamWaitEvent(0, g_join, 0);

    gatherH_kernel<<<(NNODES * 32 + 255) / 256, 256>>>(bl1);
    gemm2_kernel<<<GRID2, 256, G2_SMEM>>>(Wl2, Wr2, bl2);
    gather2_final_kernel<<<(NNODES * 32 + 255) / 256, 256>>>(out);
}